// round 5
// baseline (speedup 1.0000x reference)
#include <cuda_runtime.h>
#include <cuda_fp16.h>
#include <cstdint>

#define K  256
#define TT 1024
#define BB 64
#define LN2F 0.6931471805599453f

// ET packed half2 per (rank, c, tid): thread tid of CTA rank r, j = r*128+tid.
// c<64: own-half  i0 = r*128 + 2c
// c>=64: peer-half i0 = (1-r)*128 + 2*(c-64)
// value = half2(exp(tr[i0][j]), exp(tr[i0+1][j]))
__device__ uint32_t g_ETh[2 * 128 * 128];   // 64K u32 = 256KB? no: 2*128*128=32768 *4B = 128KB
__device__ float g_num[BB];
__device__ float g_half[2 * BB];

// ---------------------------------------------------------------------------
// PTX helpers
// ---------------------------------------------------------------------------
__device__ __forceinline__ uint32_t smem_u32(const void* p) {
    uint32_t a;
    asm("{ .reg .u64 t; cvta.to.shared.u64 t, %1; cvt.u32.u64 %0, t; }"
        : "=r"(a) : "l"(p));
    return a;
}
__device__ __forceinline__ uint32_t mapa_u32(uint32_t a, uint32_t r) {
    uint32_t d;
    asm("mapa.shared::cluster.u32 %0, %1, %2;" : "=r"(d) : "r"(a), "r"(r));
    return d;
}
__device__ __forceinline__ void st_async32(uint32_t raddr, uint32_t v, uint32_t rmbar) {
    asm volatile("st.async.shared::cluster.mbarrier::complete_tx::bytes.b32 [%0], %1, [%2];"
                 :: "r"(raddr), "r"(v), "r"(rmbar) : "memory");
}
__device__ __forceinline__ void mbar_init(uint32_t addr, uint32_t cnt) {
    asm volatile("mbarrier.init.shared.b64 [%0], %1;" :: "r"(addr), "r"(cnt) : "memory");
}
__device__ __forceinline__ void mbar_arm(uint32_t addr, uint32_t bytes) {
    asm volatile("mbarrier.arrive.expect_tx.shared.b64 _, [%0], %1;"
                 :: "r"(addr), "r"(bytes) : "memory");
}
__device__ __forceinline__ void mbar_wait(uint32_t addr, uint32_t parity) {
    asm volatile(
        "{\n\t.reg .pred P;\n\t"
        "WL%=:\n\t"
        "mbarrier.try_wait.parity.acquire.cluster.shared::cta.b64 P, [%0], %1, 0x989680;\n\t"
        "@P bra WD%=;\n\t"
        "bra WL%=;\n\t"
        "WD%=:\n\t}"
        :: "r"(addr), "r"(parity) : "memory");
}
__device__ __forceinline__ void cluster_sync_() {
    asm volatile("barrier.cluster.arrive.aligned;" ::: "memory");
    asm volatile("barrier.cluster.wait.aligned;" ::: "memory");
}
__device__ __forceinline__ uint32_t ctarank_() {
    uint32_t r; asm("mov.u32 %0, %%cluster_ctarank;" : "=r"(r)); return r;
}
__device__ __forceinline__ __half2 u2h(uint32_t u) {
    return *reinterpret_cast<__half2*>(&u);
}

// ---------------------------------------------------------------------------
__global__ void pack_kernel(const float* __restrict__ tr) {
    int idx = blockIdx.x * blockDim.x + threadIdx.x;   // 0..32767
    if (idx >= 2 * 128 * 128) return;
    int r   = idx >> 14;
    int c   = (idx >> 7) & 127;
    int tid = idx & 127;
    int j  = (r << 7) + tid;
    int i0 = (c < 64) ? ((r << 7) + 2 * c) : (((1 - r) << 7) + 2 * (c - 64));
    float e0 = __expf(tr[i0 * K + j]);
    float e1 = __expf(tr[(i0 + 1) * K + j]);
    __half2 h = __floats2half2_rn(e0, e1);
    g_ETh[idx] = *reinterpret_cast<uint32_t*>(&h);
}

// ---------------------------------------------------------------------------
__global__ void num_kernel(const float* __restrict__ inputs,
                           const long long* __restrict__ tags,
                           const int* __restrict__ mask,
                           const float* __restrict__ tr,
                           const float* __restrict__ starttr,
                           const float* __restrict__ endtr) {
    int b = blockIdx.x;
    int tid = threadIdx.x;                  // 256
    __shared__ float redf[8];
    __shared__ int   redi[8];
    const float* lg = inputs + (size_t)b * TT * K;
    const long long* tg = tags + (size_t)b * TT;

    float partial = 0.0f;
    int lenp = 0;
    for (int t = tid; t < TT; t += 256) {
        int m = mask[b * TT + t];
        lenp += m;
        if (t > 0 && m) {
            int tt = (int)tg[t];
            int tp = (int)tg[t - 1];
            partial += lg[(size_t)t * K + tt] + tr[tp * K + tt];
        }
    }
    #pragma unroll
    for (int o = 16; o; o >>= 1) {
        partial += __shfl_xor_sync(0xFFFFFFFFu, partial, o);
        lenp    += __shfl_xor_sync(0xFFFFFFFFu, lenp, o);
    }
    if ((tid & 31) == 0) { redf[tid >> 5] = partial; redi[tid >> 5] = lenp; }
    __syncthreads();
    if (tid == 0) {
        float s = 0.0f; int len = 0;
        #pragma unroll
        for (int w = 0; w < 8; w++) { s += redf[w]; len += redi[w]; }
        int t0 = (int)tg[0];
        int lastt = (int)tg[len - 1];
        s += lg[t0] + starttr[t0] + endtr[lastt];
        g_num[b] = s;
    }
}

// ---------------------------------------------------------------------------
// Scan kernel: 2-CTA cluster per batch, 128 threads per CTA (1 thread per j).
// Each thread holds the full 256-i ET column in registers (128 half2).
// Own i-half matvec first (hides the DSMEM flight), then peer half from rbuf.
// Cross-CTA scaling via integer exponent deltas (exact 2^d folds).
// ---------------------------------------------------------------------------
__global__ void __launch_bounds__(128, 1) __cluster_dims__(2, 1, 1)
scan_kernel(const float* __restrict__ inputs,
            const int* __restrict__ mask,
            const float* __restrict__ starttr,
            const float* __restrict__ endtr) {
    __shared__ __align__(16) __half   pbuf[2][128];   // own p halves, double-buffered
    __shared__ __align__(16) uint32_t rbuf[2][68];    // recv: 64 packed half2 + E + pad
    __shared__ __align__(16) uint32_t wmaxS[2][4];
    __shared__ float redf[4];
    __shared__ int   msum[4];
    __shared__ float m0S;
    __shared__ __align__(8) uint64_t mbarF[2];
    __shared__ __align__(8) uint64_t mbarM;
    __shared__ int maskS[TT];

    const int tid = threadIdx.x;           // 0..127
    const int w   = tid >> 5;
    const uint32_t rank = ctarank_();
    const int b  = blockIdx.x >> 1;
    const int jg = ((int)rank << 7) + tid;

    // ET column into registers (128 half2): own c<64, peer c>=64.
    uint32_t et[128];
    #pragma unroll
    for (int c = 0; c < 128; c++) et[c] = g_ETh[((int)rank << 14) + (c << 7) + tid];

    if (tid == 0) {
        mbar_init(smem_u32(&mbarF[0]), 1);
        mbar_init(smem_u32(&mbarF[1]), 1);
        mbar_init(smem_u32(&mbarM), 1);
        mbar_arm(smem_u32(&mbarF[0]), 260);
        mbar_arm(smem_u32(&mbarF[1]), 260);
        mbar_arm(smem_u32(&mbarM), 4);
    }

    // mask + length
    int lenp = 0;
    #pragma unroll
    for (int t = tid; t < TT; t += 128) {
        int m = mask[b * TT + t];
        maskS[t] = m;
        lenp += m;
    }
    #pragma unroll
    for (int o = 16; o; o >>= 1) lenp += __shfl_xor_sync(0xFFFFFFFFu, lenp, o);
    if ((tid & 31) == 0) msum[w] = lenp;
    __syncthreads();
    int len = msum[0] + msum[1] + msum[2] + msum[3];
    const int endidx = len - 1;

    cluster_sync_();   // mbarriers armed + visible before any st.async

    const uint32_t peer = rank ^ 1u;
    const uint32_t mb0 = smem_u32(&mbarF[0]);
    const uint32_t mb1 = smem_u32(&mbarF[1]);
    const uint32_t rm_mbar[2] = { mapa_u32(mb0, peer), mapa_u32(mb1, peer) };
    const uint32_t rm_rbuf[2] = { mapa_u32(smem_u32(&rbuf[0][0]), peer),
                                  mapa_u32(smem_u32(&rbuf[1][0]), peer) };
    const uint32_t rm_mbarM = mapa_u32(smem_u32(&mbarM), peer);
    const uint32_t rm_m0    = mapa_u32(smem_u32(&m0S), peer);

    const float* lgbase = inputs + (size_t)b * TT * K;
    const float  ej     = endtr[jg];
    const float  ejExp  = __expf(ej);

    // ---- Prologue: global m0 via one exchange, p(0) -> stage 0 ----
    float a = lgbase[jg] + starttr[jg] + (endidx == 0 ? ej : 0.0f);
    {
        float v = a;
        #pragma unroll
        for (int o = 16; o; o >>= 1) v = fmaxf(v, __shfl_xor_sync(0xFFFFFFFFu, v, o));
        if ((tid & 31) == 0) redf[w] = v;
    }
    __syncthreads();
    float m0loc = fmaxf(fmaxf(redf[0], redf[1]), fmaxf(redf[2], redf[3]));
    if (tid == 0) st_async32(rm_m0, __float_as_uint(m0loc), rm_mbarM);
    mbar_wait(smem_u32(&mbarM), 0u);
    float m0 = fmaxf(m0loc, m0S);

    float p0 = __expf(a - m0);
    __half hp = __float2half(p0);
    float  phf = p0;
    int    E = 0;
    pbuf[0][tid] = hp;
    uint32_t wm = __reduce_max_sync(0xFFFFFFFFu, __float_as_uint(p0));
    if ((tid & 31) == 0) wmaxS[0][w] = wm;
    // send p(0) + E to peer stage 0
    {
        uint32_t hu = (uint32_t)__half_as_ushort(hp);
        uint32_t up = __shfl_down_sync(0xFFFFFFFFu, hu, 1);
        if (!(tid & 1))
            st_async32(rm_rbuf[0] + (uint32_t)(tid >> 1) * 4u, hu | (up << 16), rm_mbar[0]);
        if (tid == 0)
            st_async32(rm_rbuf[0] + 256u, (uint32_t)E, rm_mbar[0]);
    }
    float lg0 = lgbase[K + jg];
    float lg1 = lgbase[2 * K + jg];
    __syncthreads();   // pbuf[0]/wmaxS[0] visible

    // ---- Main loop ----
    for (int t = 1; t < TT; t++) {
        const int v  = (t - 1) & 1;
        const int sn = t & 1;

        // hoists: prev stored-max fold -> scale; exp(logit)
        uint4 wv = *reinterpret_cast<const uint4*>(&wmaxS[v][0]);
        uint32_t m = wv.x > wv.y ? wv.x : wv.y;
        uint32_t m2 = wv.z > wv.w ? wv.z : wv.w;
        m = m > m2 ? m : m2;
        int eb = (int)((m >> 23) & 0xFF);
        float scale = __uint_as_float((uint32_t)(254 - eb) << 23);  // 2^(127-eb)
        float el = __expf(lg0);

        // own-half matvec (chunks 0..7) on pbuf[v]
        const uint4* pb4 = reinterpret_cast<const uint4*>(&pbuf[v][0]);
        float svOwn = 0.0f;
        #pragma unroll
        for (int cc = 0; cc < 8; cc++) {
            uint4 u0 = pb4[2 * cc];
            uint4 u1 = pb4[2 * cc + 1];
            __half2 acc = __float2half2_rn(0.0f);
            acc = __hfma2(u2h(et[8 * cc + 0]), u2h(u0.x), acc);
            acc = __hfma2(u2h(et[8 * cc + 1]), u2h(u0.y), acc);
            acc = __hfma2(u2h(et[8 * cc + 2]), u2h(u0.z), acc);
            acc = __hfma2(u2h(et[8 * cc + 3]), u2h(u0.w), acc);
            acc = __hfma2(u2h(et[8 * cc + 4]), u2h(u1.x), acc);
            acc = __hfma2(u2h(et[8 * cc + 5]), u2h(u1.y), acc);
            acc = __hfma2(u2h(et[8 * cc + 6]), u2h(u1.z), acc);
            acc = __hfma2(u2h(et[8 * cc + 7]), u2h(u1.w), acc);
            float2 f = __half22float2(acc);
            svOwn += f.x + f.y;
        }

        // wait peer p(t-1); re-arm for the completion after next
        mbar_wait(v ? mb1 : mb0, (uint32_t)(((t - 1) >> 1) & 1));
        if (tid == 0) mbar_arm(v ? mb1 : mb0, 260);

        int Epeer = (int)rbuf[v][64];
        int d = Epeer - E;
        d = d < -126 ? -126 : (d > 126 ? 126 : d);
        float p2d = __uint_as_float((uint32_t)(127 + d) << 23);

        // peer-half matvec (chunks 8..15) on rbuf[v]
        const uint4* rb4 = reinterpret_cast<const uint4*>(&rbuf[v][0]);
        float svPeer = 0.0f;
        #pragma unroll
        for (int cc = 0; cc < 8; cc++) {
            uint4 u0 = rb4[2 * cc];
            uint4 u1 = rb4[2 * cc + 1];
            __half2 acc = __float2half2_rn(0.0f);
            acc = __hfma2(u2h(et[64 + 8 * cc + 0]), u2h(u0.x), acc);
            acc = __hfma2(u2h(et[64 + 8 * cc + 1]), u2h(u0.y), acc);
            acc = __hfma2(u2h(et[64 + 8 * cc + 2]), u2h(u0.z), acc);
            acc = __hfma2(u2h(et[64 + 8 * cc + 3]), u2h(u0.w), acc);
            acc = __hfma2(u2h(et[64 + 8 * cc + 4]), u2h(u1.x), acc);
            acc = __hfma2(u2h(et[64 + 8 * cc + 5]), u2h(u1.y), acc);
            acc = __hfma2(u2h(et[64 + 8 * cc + 6]), u2h(u1.z), acc);
            acc = __hfma2(u2h(et[64 + 8 * cc + 7]), u2h(u1.w), acc);
            float2 f = __half22float2(acc);
            svPeer += f.x + f.y;
        }

        if (maskS[t]) {
            float sv = fmaf(svPeer, p2d, svOwn);
            float q = sv * el;
            if (t == endidx) q *= ejExp;
            float qs = q * scale;                 // exact pow2
            wm = __reduce_max_sync(0xFFFFFFFFu, __float_as_uint(qs));
            hp = __float2half(qs);
            phf = qs;
            E += eb - 127;
        }
        pbuf[sn][tid] = hp;
        if ((tid & 31) == 0) wmaxS[sn][w] = wm;

        if (t != TT - 1) {
            uint32_t hu = (uint32_t)__half_as_ushort(hp);
            uint32_t up = __shfl_down_sync(0xFFFFFFFFu, hu, 1);
            if (!(tid & 1))
                st_async32(rm_rbuf[sn] + (uint32_t)(tid >> 1) * 4u, hu | (up << 16),
                           rm_mbar[sn]);
            if (tid == 0)
                st_async32(rm_rbuf[sn] + 256u, (uint32_t)E, rm_mbar[sn]);
        }

        lg0 = lg1;
        lg1 = (t + 2 < TT) ? lgbase[(size_t)(t + 2) * K + jg] : 0.0f;

        __syncthreads();
    }

    // ---- half-denominator ----
    float vsum = phf;
    #pragma unroll
    for (int o = 16; o; o >>= 1) vsum += __shfl_xor_sync(0xFFFFFFFFu, vsum, o);
    if ((tid & 31) == 0) redf[w] = vsum;
    __syncthreads();
    if (tid == 0) {
        float S = redf[0] + redf[1] + redf[2] + redf[3];
        g_half[(b << 1) | (int)rank] = m0 + (float)E * LN2F + logf(S);
    }
    cluster_sync_();   // don't exit while peer st.async may be in flight
}

// ---------------------------------------------------------------------------
__global__ void final_kernel(float* __restrict__ out) {
    int tid = threadIdx.x;                       // 64 threads
    float a0 = g_half[2 * tid];
    float a1 = g_half[2 * tid + 1];
    float mx = fmaxf(a0, a1);
    float den = mx + logf(__expf(a0 - mx) + __expf(a1 - mx));
    float v = g_num[tid] - den;
    #pragma unroll
    for (int o = 16; o; o >>= 1) v += __shfl_xor_sync(0xFFFFFFFFu, v, o);
    __shared__ float r[2];
    if ((tid & 31) == 0) r[tid >> 5] = v;
    __syncthreads();
    if (tid == 0) out[0] = r[0] + r[1];
}

// ---------------------------------------------------------------------------
extern "C" void kernel_launch(void* const* d_in, const int* in_sizes, int n_in,
                              void* d_out, int out_size) {
    const float*     inputs = (const float*)d_in[0];
    const long long* tags   = (const long long*)d_in[1];
    const int*       mask   = (const int*)d_in[2];
    const float*     tr     = (const float*)d_in[3];
    const float*     st     = (const float*)d_in[4];
    const float*     en     = (const float*)d_in[5];
    float* out = (float*)d_out;

    (void)in_sizes; (void)n_in; (void)out_size;

    pack_kernel<<<128, 256>>>(tr);
    num_kernel<<<BB, 256>>>(inputs, tags, mask, tr, st, en);
    scan_kernel<<<2 * BB, 128>>>(inputs, mask, st, en);
    final_kernel<<<1, 64>>>(out);
}

// round 6
// speedup vs baseline: 1.0399x; 1.0399x over previous
#include <cuda_runtime.h>
#include <cuda_fp16.h>
#include <cstdint>

#define K  256
#define TT 1024
#define BB 64
#define LN2F 0.6931471805599453f

// ET packed half2 per (rank, c, tid): CTA rank r, thread tid (0..255):
//   part = tid&1, jl = tid>>1, j = r*128 + jl
//   c < 32 : own-half  i0 = r*128     + part*64 + 2c
//   c >= 32: peer-half i0 = (1-r)*128 + part*64 + 2(c-32)
//   value = half2(exp(tr[i0][j]), exp(tr[i0+1][j]))
__device__ uint32_t g_ETh[2 * 64 * 256];   // 32768 u32 = 128KB
__device__ float g_num[BB];
__device__ float g_half[2 * BB];

// ---------------------------------------------------------------------------
// PTX helpers
// ---------------------------------------------------------------------------
__device__ __forceinline__ uint32_t smem_u32(const void* p) {
    uint32_t a;
    asm("{ .reg .u64 t; cvta.to.shared.u64 t, %1; cvt.u32.u64 %0, t; }"
        : "=r"(a) : "l"(p));
    return a;
}
__device__ __forceinline__ uint32_t mapa_u32(uint32_t a, uint32_t r) {
    uint32_t d;
    asm("mapa.shared::cluster.u32 %0, %1, %2;" : "=r"(d) : "r"(a), "r"(r));
    return d;
}
__device__ __forceinline__ void st_async32(uint32_t raddr, uint32_t v, uint32_t rmbar) {
    asm volatile("st.async.shared::cluster.mbarrier::complete_tx::bytes.b32 [%0], %1, [%2];"
                 :: "r"(raddr), "r"(v), "r"(rmbar) : "memory");
}
__device__ __forceinline__ void mbar_init(uint32_t addr, uint32_t cnt) {
    asm volatile("mbarrier.init.shared.b64 [%0], %1;" :: "r"(addr), "r"(cnt) : "memory");
}
__device__ __forceinline__ void mbar_arm(uint32_t addr, uint32_t bytes) {
    asm volatile("mbarrier.arrive.expect_tx.shared.b64 _, [%0], %1;"
                 :: "r"(addr), "r"(bytes) : "memory");
}
__device__ __forceinline__ void mbar_wait(uint32_t addr, uint32_t parity) {
    asm volatile(
        "{\n\t.reg .pred P;\n\t"
        "WL%=:\n\t"
        "mbarrier.try_wait.parity.acquire.cluster.shared::cta.b64 P, [%0], %1, 0x989680;\n\t"
        "@P bra WD%=;\n\t"
        "bra WL%=;\n\t"
        "WD%=:\n\t}"
        :: "r"(addr), "r"(parity) : "memory");
}
__device__ __forceinline__ void cluster_sync_() {
    asm volatile("barrier.cluster.arrive.aligned;" ::: "memory");
    asm volatile("barrier.cluster.wait.aligned;" ::: "memory");
}
__device__ __forceinline__ uint32_t ctarank_() {
    uint32_t r; asm("mov.u32 %0, %%cluster_ctarank;" : "=r"(r)); return r;
}
__device__ __forceinline__ __half2 u2h(uint32_t u) {
    return *reinterpret_cast<__half2*>(&u);
}

// ---------------------------------------------------------------------------
__global__ void pack_kernel(const float* __restrict__ tr) {
    int idx = blockIdx.x * blockDim.x + threadIdx.x;   // 0..32767
    if (idx >= 2 * 64 * 256) return;
    int r   = idx >> 14;
    int c   = (idx >> 8) & 63;
    int tid = idx & 255;
    int part = tid & 1;
    int jl   = tid >> 1;
    int j  = (r << 7) + jl;
    int i0 = (c < 32) ? ((r << 7) + (part << 6) + 2 * c)
                      : (((1 - r) << 7) + (part << 6) + 2 * (c - 32));
    float e0 = __expf(tr[i0 * K + j]);
    float e1 = __expf(tr[(i0 + 1) * K + j]);
    __half2 h = __floats2half2_rn(e0, e1);
    g_ETh[idx] = *reinterpret_cast<uint32_t*>(&h);
}

// ---------------------------------------------------------------------------
__global__ void num_kernel(const float* __restrict__ inputs,
                           const long long* __restrict__ tags,
                           const int* __restrict__ mask,
                           const float* __restrict__ tr,
                           const float* __restrict__ starttr,
                           const float* __restrict__ endtr) {
    int b = blockIdx.x;
    int tid = threadIdx.x;                  // 256
    __shared__ float redf[8];
    __shared__ int   redi[8];
    const float* lg = inputs + (size_t)b * TT * K;
    const long long* tg = tags + (size_t)b * TT;

    float partial = 0.0f;
    int lenp = 0;
    for (int t = tid; t < TT; t += 256) {
        int m = mask[b * TT + t];
        lenp += m;
        if (t > 0 && m) {
            int tt = (int)tg[t];
            int tp = (int)tg[t - 1];
            partial += lg[(size_t)t * K + tt] + tr[tp * K + tt];
        }
    }
    #pragma unroll
    for (int o = 16; o; o >>= 1) {
        partial += __shfl_xor_sync(0xFFFFFFFFu, partial, o);
        lenp    += __shfl_xor_sync(0xFFFFFFFFu, lenp, o);
    }
    if ((tid & 31) == 0) { redf[tid >> 5] = partial; redi[tid >> 5] = lenp; }
    __syncthreads();
    if (tid == 0) {
        float s = 0.0f; int len = 0;
        #pragma unroll
        for (int w = 0; w < 8; w++) { s += redf[w]; len += redi[w]; }
        int t0 = (int)tg[0];
        int lastt = (int)tg[len - 1];
        s += lg[t0] + starttr[t0] + endtr[lastt];
        g_num[b] = s;
    }
}

// ---------------------------------------------------------------------------
// Scan kernel: 2-CTA cluster per batch, 256 threads per CTA.
// Thread pair (2*jl, 2*jl+1) splits the 256-i column of j = rank*128+jl:
// each thread does 64 i's (32 HFMA2), combined with one shfl_xor.
// Own i-half first (hides DSMEM flight), then peer half from rbuf.
// Cross-CTA scaling via integer exponent deltas (exact 2^d folds).
// ---------------------------------------------------------------------------
__global__ void __launch_bounds__(256, 1) __cluster_dims__(2, 1, 1)
scan_kernel(const float* __restrict__ inputs,
            const int* __restrict__ mask,
            const float* __restrict__ starttr,
            const float* __restrict__ endtr) {
    __shared__ __align__(16) __half   pbuf[2][128];   // own p half, double-buffered
    __shared__ __align__(16) uint32_t rbuf[2][68];    // recv: 64 packed half2 + E
    __shared__ __align__(16) uint32_t wmaxS[2][8];
    __shared__ float redf[8];
    __shared__ int   msum[8];
    __shared__ float m0S;
    __shared__ __align__(8) uint64_t mbarF[2];
    __shared__ __align__(8) uint64_t mbarM;
    __shared__ int maskS[TT];

    const int tid  = threadIdx.x;          // 0..255
    const int w    = tid >> 5;
    const int part = tid & 1;
    const int jl   = tid >> 1;
    const uint32_t rank = ctarank_();
    const int b  = blockIdx.x >> 1;
    const int jg = ((int)rank << 7) + jl;

    // ET slice into registers: 64 half2 (own 0..31, peer 32..63), coalesced.
    uint32_t et[64];
    #pragma unroll
    for (int c = 0; c < 64; c++) et[c] = g_ETh[((int)rank << 14) + (c << 8) + tid];

    if (tid == 0) {
        mbar_init(smem_u32(&mbarF[0]), 1);
        mbar_init(smem_u32(&mbarF[1]), 1);
        mbar_init(smem_u32(&mbarM), 1);
        mbar_arm(smem_u32(&mbarF[0]), 260);
        mbar_arm(smem_u32(&mbarF[1]), 260);
        mbar_arm(smem_u32(&mbarM), 4);
    }

    // mask + length
    int lenp = 0;
    #pragma unroll
    for (int t = tid; t < TT; t += 256) {
        int m = mask[b * TT + t];
        maskS[t] = m;
        lenp += m;
    }
    #pragma unroll
    for (int o = 16; o; o >>= 1) lenp += __shfl_xor_sync(0xFFFFFFFFu, lenp, o);
    if ((tid & 31) == 0) msum[w] = lenp;
    __syncthreads();
    int len = 0;
    #pragma unroll
    for (int q8 = 0; q8 < 8; q8++) len += msum[q8];
    const int endidx = len - 1;

    cluster_sync_();   // mbarriers armed + visible before any st.async

    const uint32_t peer = rank ^ 1u;
    const uint32_t mb0 = smem_u32(&mbarF[0]);
    const uint32_t mb1 = smem_u32(&mbarF[1]);
    const uint32_t rm_mbar[2] = { mapa_u32(mb0, peer), mapa_u32(mb1, peer) };
    const uint32_t rm_rbuf[2] = { mapa_u32(smem_u32(&rbuf[0][0]), peer),
                                  mapa_u32(smem_u32(&rbuf[1][0]), peer) };
    const uint32_t rm_mbarM = mapa_u32(smem_u32(&mbarM), peer);
    const uint32_t rm_m0    = mapa_u32(smem_u32(&m0S), peer);

    const float* lgbase = inputs + (size_t)b * TT * K;
    const float  ej     = endtr[jg];
    const float  ejExp  = __expf(ej);

    // ---- Prologue: global m0 via one exchange; p(0) -> stage 0 ----
    float a = lgbase[jg] + starttr[jg] + (endidx == 0 ? ej : 0.0f);
    {
        float v = a;
        #pragma unroll
        for (int o = 16; o; o >>= 1) v = fmaxf(v, __shfl_xor_sync(0xFFFFFFFFu, v, o));
        if ((tid & 31) == 0) redf[w] = v;
    }
    __syncthreads();
    float m0loc = redf[0];
    #pragma unroll
    for (int q8 = 1; q8 < 8; q8++) m0loc = fmaxf(m0loc, redf[q8]);
    if (tid == 0) st_async32(rm_m0, __float_as_uint(m0loc), rm_mbarM);
    mbar_wait(smem_u32(&mbarM), 0u);
    float m0 = fmaxf(m0loc, m0S);

    float p0 = __expf(a - m0);
    __half hp = __float2half(p0);
    float  phf = p0;
    int    E = 0;
    if (!part) pbuf[0][jl] = hp;
    uint32_t wm = __reduce_max_sync(0xFFFFFFFFu, __float_as_uint(p0));
    if ((tid & 31) == 0) wmaxS[0][w] = wm;
    {
        uint32_t hu = (uint32_t)__half_as_ushort(hp);
        uint32_t h2 = __shfl_down_sync(0xFFFFFFFFu, hu, 2);
        if ((tid & 3) == 0)
            st_async32(rm_rbuf[0] + (uint32_t)(tid >> 2) * 4u, hu | (h2 << 16), rm_mbar[0]);
        if (tid == 0)
            st_async32(rm_rbuf[0] + 256u, (uint32_t)E, rm_mbar[0]);
    }
    float lg0 = lgbase[K + jg];
    float lg1 = lgbase[2 * K + jg];
    __syncthreads();   // pbuf[0]/wmaxS[0] visible

    const uint32_t pByte = (uint32_t)(part << 7);   // byte offset of this thread's i-range

    // ---- Main loop ----
    for (int t = 1; t < TT; t++) {
        const int v  = (t - 1) & 1;
        const int sn = t & 1;

        // hoists: prev stored-max fold -> scale; exp(logit)
        uint4 wa = *reinterpret_cast<const uint4*>(&wmaxS[v][0]);
        uint4 wb = *reinterpret_cast<const uint4*>(&wmaxS[v][4]);
        uint32_t m  = wa.x > wa.y ? wa.x : wa.y;
        uint32_t m2 = wa.z > wa.w ? wa.z : wa.w;
        uint32_t m3 = wb.x > wb.y ? wb.x : wb.y;
        uint32_t m4 = wb.z > wb.w ? wb.z : wb.w;
        m = m > m2 ? m : m2; m3 = m3 > m4 ? m3 : m4;
        m = m > m3 ? m : m3;
        int eb = (int)((m >> 23) & 0xFF);
        float scale = __uint_as_float((uint32_t)(254 - eb) << 23);  // 2^(127-eb)
        float el = __expf(lg0);

        // own-half matvec (et[0..31]) on pbuf[v] + pByte
        const uint4* pb4 = reinterpret_cast<const uint4*>(
            reinterpret_cast<const char*>(&pbuf[v][0]) + pByte);
        float svOwn = 0.0f;
        #pragma unroll
        for (int g = 0; g < 4; g++) {           // 4 chunks x 16 i
            uint4 u0 = pb4[2 * g];
            uint4 u1 = pb4[2 * g + 1];
            __half2 acc = __float2half2_rn(0.0f);
            acc = __hfma2(u2h(et[8 * g + 0]), u2h(u0.x), acc);
            acc = __hfma2(u2h(et[8 * g + 1]), u2h(u0.y), acc);
            acc = __hfma2(u2h(et[8 * g + 2]), u2h(u0.z), acc);
            acc = __hfma2(u2h(et[8 * g + 3]), u2h(u0.w), acc);
            acc = __hfma2(u2h(et[8 * g + 4]), u2h(u1.x), acc);
            acc = __hfma2(u2h(et[8 * g + 5]), u2h(u1.y), acc);
            acc = __hfma2(u2h(et[8 * g + 6]), u2h(u1.z), acc);
            acc = __hfma2(u2h(et[8 * g + 7]), u2h(u1.w), acc);
            float2 f = __half22float2(acc);
            svOwn += f.x + f.y;
        }

        // wait peer p(t-1); re-arm for the completion after next
        mbar_wait(v ? mb1 : mb0, (uint32_t)(((t - 1) >> 1) & 1));
        if (tid == 0) mbar_arm(v ? mb1 : mb0, 260);

        int Epeer = (int)rbuf[v][64];
        int d = Epeer - E;
        d = d < -126 ? -126 : (d > 126 ? 126 : d);
        float p2d = __uint_as_float((uint32_t)(127 + d) << 23);

        // peer-half matvec (et[32..63]) on rbuf[v] + pByte
        const uint4* rb4 = reinterpret_cast<const uint4*>(
            reinterpret_cast<const char*>(&rbuf[v][0]) + pByte);
        float svPeer = 0.0f;
        #pragma unroll
        for (int g = 0; g < 4; g++) {
            uint4 u0 = rb4[2 * g];
            uint4 u1 = rb4[2 * g + 1];
            __half2 acc = __float2half2_rn(0.0f);
            acc = __hfma2(u2h(et[32 + 8 * g + 0]), u2h(u0.x), acc);
            acc = __hfma2(u2h(et[32 + 8 * g + 1]), u2h(u0.y), acc);
            acc = __hfma2(u2h(et[32 + 8 * g + 2]), u2h(u0.z), acc);
            acc = __hfma2(u2h(et[32 + 8 * g + 3]), u2h(u0.w), acc);
            acc = __hfma2(u2h(et[32 + 8 * g + 4]), u2h(u1.x), acc);
            acc = __hfma2(u2h(et[32 + 8 * g + 5]), u2h(u1.y), acc);
            acc = __hfma2(u2h(et[32 + 8 * g + 6]), u2h(u1.z), acc);
            acc = __hfma2(u2h(et[32 + 8 * g + 7]), u2h(u1.w), acc);
            float2 f = __half22float2(acc);
            svPeer += f.x + f.y;
        }

        // pair combine: both lanes of (2jl, 2jl+1) get the full sum
        float sv = fmaf(svPeer, p2d, svOwn);
        sv += __shfl_xor_sync(0xFFFFFFFFu, sv, 1);

        if (maskS[t]) {
            float q = sv * el;
            if (t == endidx) q *= ejExp;
            float qs = q * scale;                 // exact pow2
            wm = __reduce_max_sync(0xFFFFFFFFu, __float_as_uint(qs));
            hp = __float2half(qs);
            phf = qs;
            E += eb - 127;
        }
        if (!part) pbuf[sn][jl] = hp;
        if ((tid & 31) == 0) wmaxS[sn][w] = wm;

        if (t != TT - 1) {
            uint32_t hu = (uint32_t)__half_as_ushort(hp);
            uint32_t h2 = __shfl_down_sync(0xFFFFFFFFu, hu, 2);
            if ((tid & 3) == 0)
                st_async32(rm_rbuf[sn] + (uint32_t)(tid >> 2) * 4u, hu | (h2 << 16),
                           rm_mbar[sn]);
            if (tid == 0)
                st_async32(rm_rbuf[sn] + 256u, (uint32_t)E, rm_mbar[sn]);
        }

        lg0 = lg1;
        lg1 = (t + 2 < TT) ? lgbase[(size_t)(t + 2) * K + jg] : 0.0f;

        __syncthreads();
    }

    // ---- half-denominator (each j counted once: part 0 lanes only) ----
    float vsum = part ? 0.0f : phf;
    #pragma unroll
    for (int o = 16; o; o >>= 1) vsum += __shfl_xor_sync(0xFFFFFFFFu, vsum, o);
    if ((tid & 31) == 0) redf[w] = vsum;
    __syncthreads();
    if (tid == 0) {
        float S = 0.0f;
        #pragma unroll
        for (int q8 = 0; q8 < 8; q8++) S += redf[q8];
        g_half[(b << 1) | (int)rank] = m0 + (float)E * LN2F + logf(S);
    }
    cluster_sync_();   // don't exit while peer st.async may be in flight
}

// ---------------------------------------------------------------------------
__global__ void final_kernel(float* __restrict__ out) {
    int tid = threadIdx.x;                       // 64 threads
    float a0 = g_half[2 * tid];
    float a1 = g_half[2 * tid + 1];
    float mx = fmaxf(a0, a1);
    float den = mx + logf(__expf(a0 - mx) + __expf(a1 - mx));
    float v = g_num[tid] - den;
    #pragma unroll
    for (int o = 16; o; o >>= 1) v += __shfl_xor_sync(0xFFFFFFFFu, v, o);
    __shared__ float r[2];
    if ((tid & 31) == 0) r[tid >> 5] = v;
    __syncthreads();
    if (tid == 0) out[0] = r[0] + r[1];
}

// ---------------------------------------------------------------------------
extern "C" void kernel_launch(void* const* d_in, const int* in_sizes, int n_in,
                              void* d_out, int out_size) {
    const float*     inputs = (const float*)d_in[0];
    const long long* tags   = (const long long*)d_in[1];
    const int*       mask   = (const int*)d_in[2];
    const float*     tr     = (const float*)d_in[3];
    const float*     st     = (const float*)d_in[4];
    const float*     en     = (const float*)d_in[5];
    float* out = (float*)d_out;

    (void)in_sizes; (void)n_in; (void)out_size;

    pack_kernel<<<128, 256>>>(tr);
    num_kernel<<<BB, 256>>>(inputs, tags, mask, tr, st, en);
    scan_kernel<<<2 * BB, 256>>>(inputs, mask, st, en);
    final_kernel<<<1, 64>>>(out);
}